// round 6
// baseline (speedup 1.0000x reference)
#include <cuda_runtime.h>
#include <cstdint>

#define D      1024
#define HD     4096
#define LNUM   12
#define VOCAB  50257
#define NT     512
#define NWP    16
#define S_RING 12
#define SLOT_B 16384
#define SLOT_F4 1024          // float4 per slot

#define NC_A 768              // 3*1024 rows / 4
#define NC_B 512              // 1024 rows / 2
#define NC_C 1280             // (4096+1024) rows / 4
#define NC_D 1024             // 1024 rows, 1 per chunk (16KB rows)
#define NC_H 12565            // ceil(50257/4)

// ---------------- global scratch ----------------
__device__ float g_x[D];
__device__ float g_k[D];
__device__ float g_v[D];
__device__ float g_r[D];
__device__ float g_k2[HD];
__device__ float g_r2[D];

// ---------------- 2-level software grid barrier ----------------
__device__ unsigned g_bar_gen = 0;
__device__ unsigned g_leaf[8 * 128];
__device__ unsigned g_root = 0;

__device__ __forceinline__ void grid_barrier(int nb) {
    __syncthreads();
    if (threadIdx.x == 0) {
        __threadfence();
        unsigned gen = *((volatile unsigned*)&g_bar_gen);
        int leaf = blockIdx.x & 7;
        unsigned target = (unsigned)((nb >> 3) + ((blockIdx.x & 7) < (nb & 7) ? 1 : 0));
        if (atomicAdd(&g_leaf[leaf * 128], 1u) == target - 1u) {
            g_leaf[leaf * 128] = 0;
            __threadfence();
            if (atomicAdd(&g_root, 1u) == 7u) {
                g_root = 0;
                __threadfence();
                atomicAdd(&g_bar_gen, 1u);
            }
        }
        while (*((volatile unsigned*)&g_bar_gen) == gen) { }
        __threadfence();
    }
    __syncthreads();
}

// ---------------- block-wide sum ----------------
__device__ __forceinline__ float block_sum(float v, float* sred) {
    int lane = threadIdx.x & 31, wid = threadIdx.x >> 5;
    #pragma unroll
    for (int o = 16; o; o >>= 1) v += __shfl_xor_sync(0xffffffffu, v, o);
    if (lane == 0) sred[wid] = v;
    __syncthreads();
    float t = 0.f;
    if (wid == 0) {
        t = (lane < NWP) ? sred[lane] : 0.f;
        #pragma unroll
        for (int o = 8; o; o >>= 1) t += __shfl_xor_sync(0xffffffffu, t, o);
        if (lane == 0) sred[0] = t;
    }
    __syncthreads();
    float r = sred[0];
    __syncthreads();
    return r;
}

// ---------------- chunk consume ----------------
// R rows of L floats in the slot; 16/R warps per row; warp reduces its piece.
template<int R, int L, class Fin>
__device__ __forceinline__ void consume_body(const float4* __restrict__ w4s,
                                             const float4* __restrict__ v4,
                                             int rows_eff, float* spart_buf, Fin fin) {
    const int tid = threadIdx.x;
    const int lane = tid & 31, wid = tid >> 5;
    constexpr int PW  = NWP / R;        // warps per row
    constexpr int PF4 = L / (4 * PW);   // float4 per piece
    constexpr int NK  = PF4 / 32;       // float4 per lane
    int row = wid / PW, sub = wid % PW;
    float acc = 0.f;
    if (row < rows_eff) {
        const float4* wr = w4s + row * (L / 4) + sub * PF4;
        const float4* vr = v4 + sub * PF4;
        #pragma unroll
        for (int k = 0; k < NK; k++) {
            float4 a = wr[k * 32 + lane];
            float4 b = vr[k * 32 + lane];
            acc = fmaf(a.x, b.x, acc); acc = fmaf(a.y, b.y, acc);
            acc = fmaf(a.z, b.z, acc); acc = fmaf(a.w, b.w, acc);
        }
    }
    #pragma unroll
    for (int o = 16; o; o >>= 1) acc += __shfl_xor_sync(0xffffffffu, acc, o);
    if (lane == 0) spart_buf[wid] = acc;
    __syncthreads();
    if (tid < R && tid < rows_eff) {
        float s = 0.f;
        #pragma unroll
        for (int q = 0; q < PW; q++) s += spart_buf[tid * PW + q];
        fin(tid, s);
    }
}

__global__ __launch_bounds__(NT, 1) void rwkv_persistent(
    const int*   __restrict__ ctx,
    const float* __restrict__ st_in,
    const float* __restrict__ emb,
    const float* __restrict__ ln0,
    const float* __restrict__ ln1,
    const float* __restrict__ ln2,
    const float* __restrict__ lnout,
    const float* __restrict__ tmk,
    const float* __restrict__ tmv,
    const float* __restrict__ tmr,
    const float* __restrict__ tfirst,
    const float* __restrict__ tdecay,
    const float* __restrict__ kw,
    const float* __restrict__ vw,
    const float* __restrict__ rw,
    const float* __restrict__ ow,
    const float* __restrict__ ftmk,
    const float* __restrict__ ftmr,
    const float* __restrict__ fkw,
    const float* __restrict__ fvw,
    const float* __restrict__ frw,
    const float* __restrict__ head,
    float* __restrict__ out,
    int nb)
{
    extern __shared__ float4 ring[];                 // S_RING * SLOT_F4
    __shared__ unsigned long long mbar[S_RING];
    __shared__ float vecS[3 * D];
    __shared__ float spart[2][NWP];
    __shared__ float sred[NWP];

    const int tid = threadIdx.x;
    const int bid = blockIdx.x;

    if (tid == 0) {
        #pragma unroll
        for (int s = 0; s < S_RING; s++) {
            unsigned a = (unsigned)__cvta_generic_to_shared(&mbar[s]);
            asm volatile("mbarrier.init.shared.b64 [%0], 1;" :: "r"(a));
        }
    }
    __syncthreads();

    int issued = 0, consumed = 0;

    // issue one chunk into the ring (tid 0 only; counters uniform)
    auto issue_to = [&](const float* gptr, int bytes) {
        int slot = issued % S_RING;
        if (tid == 0) {
            unsigned mb = (unsigned)__cvta_generic_to_shared(&mbar[slot]);
            unsigned sd = (unsigned)__cvta_generic_to_shared(ring + slot * SLOT_F4);
            asm volatile("mbarrier.arrive.expect_tx.shared.b64 _, [%0], %1;"
                         :: "r"(mb), "r"(bytes) : "memory");
            asm volatile("cp.async.bulk.shared::cta.global.mbarrier::complete_tx::bytes "
                         "[%0], [%1], %2, [%3];"
                         :: "r"(sd), "l"(gptr), "r"(bytes), "r"(mb) : "memory");
        }
        issued++;
    };

    auto top_up = [&](int& i_iss, int nmy, auto pb) {
        while (i_iss < nmy && issued - consumed < S_RING) {
            const float* p; int by;
            pb(i_iss, p, by);
            issue_to(p, by);
            i_iss++;
        }
    };

    // single-waiter handoff: tid0 polls the mbarrier, syncthreads releases all
    auto ring_wait = [&]() -> const float4* {
        int slot = consumed % S_RING;
        if (tid == 0) {
            unsigned ph = (unsigned)((consumed / S_RING) & 1);
            unsigned mb = (unsigned)__cvta_generic_to_shared(&mbar[slot]);
            unsigned done = 0;
            while (!done) {
                asm volatile("{\n\t.reg .pred p;\n\t"
                             "mbarrier.try_wait.parity.acquire.cta.shared::cta.b64 p, [%1], %2, 0x989680;\n\t"
                             "selp.b32 %0,1,0,p;\n\t}"
                             : "=r"(done) : "r"(mb), "r"(ph) : "memory");
            }
        }
        __syncthreads();
        return (const float4*)(ring + slot * SLOT_F4);
    };

    auto nmy_of = [&](int NC) { return bid < NC ? (NC - 1 - bid) / nb + 1 : 0; };
    const int nA = nmy_of(NC_A);
    const int nB = nmy_of(NC_B);
    const int nC = nmy_of(NC_C);
    const int nD = nmy_of(NC_D);
    const int nH = nmy_of(NC_H);

    float* out_logits = out;
    float* out_state  = out + VOCAB;
    const float4* vecS4 = (const float4*)vecS;

    // mutable weight pointers used by the issue lambdas (set before pre-issue)
    const float *kwl = kw, *vwl = vw, *rwl = rw;
    const float *owl = ow, *fkwl = fkw, *frwl = frw, *fvwl = fvw;

    auto pbA = [&](int i, const float*& p, int& by) {
        int c = bid + i * nb;
        int m = c >> 8; int lb = (c & 255) * 4;
        const float* base = (m == 0) ? kwl : ((m == 1) ? vwl : rwl);
        p = base + (size_t)lb * D; by = SLOT_B;
    };
    auto pbB = [&](int i, const float*& p, int& by) {
        int c = bid + i * nb;
        p = owl + (size_t)c * 2 * D; by = 8192;
    };
    auto pbC = [&](int i, const float*& p, int& by) {
        int c = bid + i * nb;
        p = (c < 1024) ? (fkwl + (size_t)c * 4 * D)
                       : (frwl + (size_t)(c - 1024) * 4 * D);
        by = SLOT_B;
    };
    auto pbD = [&](int i, const float*& p, int& by) {
        int c = bid + i * nb;
        p = fvwl + (size_t)c * HD; by = SLOT_B;
    };
    auto pbH = [&](int i, const float*& p, int& by) {
        int c = bid + i * nb;
        p = head + (size_t)c * 4 * D;
        int re = VOCAB - c * 4; if (re > 4) re = 4;
        by = re * 4096;
    };

    // ---------- pre-issue layer-0 stage A, compute embedding ----------
    int iA = 0, iB = 0, iC = 0, iD = 0, iH = 0;
    top_up(iA, nA, pbA);

    if (bid == 0) {
        const float* e = emb + (size_t)ctx[0] * D;
        float ss = 0.f;
        for (int j = tid; j < D; j += NT) { float t = e[j]; ss += t * t; }
        ss = block_sum(ss, sred);
        float inv = rsqrtf(ss * (1.f / D) + 1e-5f);
        for (int j = tid; j < D; j += NT) g_x[j] = e[j] * inv * ln0[j];
    }
    grid_barrier(nb);

    for (int l = 0; l < LNUM; l++) {
        const float* st_l  = st_in     + (size_t)l * 5 * D;
        float*       ost_l = out_state + (size_t)l * 5 * D;

        // ---------- stage A prep + consume (k/v/r) ----------
        {
            float ss = 0.f;
            for (int j = tid; j < D; j += NT) { float t = g_x[j]; ss += t * t; }
            ss = block_sum(ss, sred);
            float inv = rsqrtf(ss * (1.f / D) + 1e-5f);
            const float* l1 = ln1 + l * D;
            const float* mk = tmk + l * D;
            const float* mv = tmv + l * D;
            const float* mr = tmr + l * D;
            for (int j = tid; j < D; j += NT) {
                float xxj = g_x[j] * inv * l1[j];
                float sa  = st_l[D + j];
                float a_ = mk[j]; vecS[j]         = xxj * a_ + sa * (1.f - a_);
                float b_ = mv[j]; vecS[D + j]     = xxj * b_ + sa * (1.f - b_);
                float c_ = mr[j]; vecS[2 * D + j] = xxj * c_ + sa * (1.f - c_);
                if (bid == 0) ost_l[D + j] = xxj;
            }
            __syncthreads();
            for (int i = 0; i < nA; i++) {
                top_up(iA, nA, pbA);
                const float4* w4 = ring_wait();
                int c = bid + i * nb;
                int m = c >> 8;
                auto fin = [&](int r, float t) {
                    int row = c * 4 + r;
                    if (row < D)          g_k[row] = t;
                    else if (row < 2 * D) g_v[row - D] = t;
                    else                  g_r[row - 2 * D] = t;
                };
                consume_body<4, D>(w4, vecS4 + m * 256, 4, spart[i & 1], fin);
                consumed++;
            }
        }
        owl = ow + (size_t)l * D * D;
        iB = 0; top_up(iB, nB, pbB);
        grid_barrier(nb);

        // ---------- stage B prep (WKV) + consume (ow) ----------
        {
            const float* tfl = tfirst + l * D;
            const float* tdl = tdecay + l * D;
            for (int j = tid; j < D; j += NT) {
                float k  = g_k[j], v = g_v[j], rr = g_r[j];
                float aa = st_l[2 * D + j], bb = st_l[3 * D + j], pp = st_l[4 * D + j];
                float ww = tfl[j] + k;
                float p  = fmaxf(pp, ww);
                float e1 = __expf(pp - p), e2 = __expf(ww - p);
                float a  = e1 * aa + e2 * v;
                float b  = e1 * bb + e2;
                float sr = 1.f / (1.f + __expf(-rr));
                vecS[j] = sr * (a / b);
                if (bid == 0) {
                    float ww2 = pp + tdl[j];
                    float p2  = fmaxf(ww2, k);
                    float e1b = __expf(ww2 - p2), e2b = __expf(k - p2);
                    ost_l[2 * D + j] = e1b * aa + e2b * v;
                    ost_l[3 * D + j] = e1b * bb + e2b;
                    ost_l[4 * D + j] = p2;
                }
            }
            __syncthreads();
            for (int i = 0; i < nB; i++) {
                top_up(iB, nB, pbB);
                const float4* w4 = ring_wait();
                int c = bid + i * nb;
                auto fin = [&](int r, float t) { g_x[c * 2 + r] += t; };
                consume_body<2, D>(w4, vecS4, 2, spart[i & 1], fin);
                consumed++;
            }
        }
        fkwl = fkw + (size_t)l * HD * D;
        frwl = frw + (size_t)l * D * D;
        iC = 0; top_up(iC, nC, pbC);
        grid_barrier(nb);

        // ---------- stage C prep + consume (fkw / frw) ----------
        {
            float ss = 0.f;
            for (int j = tid; j < D; j += NT) { float t = g_x[j]; ss += t * t; }
            ss = block_sum(ss, sred);
            float inv = rsqrtf(ss * (1.f / D) + 1e-5f);
            const float* l2l = ln2  + l * D;
            const float* fmk = ftmk + l * D;
            const float* fmr = ftmr + l * D;
            for (int j = tid; j < D; j += NT) {
                float yyj = g_x[j] * inv * l2l[j];
                float ff  = st_l[j];
                float a_ = fmk[j]; vecS[j]     = yyj * a_ + ff * (1.f - a_);
                float b_ = fmr[j]; vecS[D + j] = yyj * b_ + ff * (1.f - b_);
                if (bid == 0) ost_l[j] = yyj;
            }
            __syncthreads();
            for (int i = 0; i < nC; i++) {
                top_up(iC, nC, pbC);
                const float4* w4 = ring_wait();
                int c = bid + i * nb;
                const float4* v4 = (c < 1024) ? vecS4 : (vecS4 + 256);
                auto fin = [&](int r, float t) {
                    if (c < 1024) {
                        t = fmaxf(t, 0.f);
                        g_k2[c * 4 + r] = t * t;
                    } else {
                        g_r2[(c - 1024) * 4 + r] = t;
                    }
                };
                consume_body<4, D>(w4, v4, 4, spart[i & 1], fin);
                consumed++;
            }
        }
        fvwl = fvw + (size_t)l * D * HD;
        iD = 0; top_up(iD, nD, pbD);
        grid_barrier(nb);

        // ---------- stage D consume (fvw, vec = g_k2 from L2) ----------
        {
            const float sc = ((l + 1) % 6 == 0) ? 0.5f : 1.0f;
            for (int i = 0; i < nD; i++) {
                top_up(iD, nD, pbD);
                const float4* w4 = ring_wait();
                int c = bid + i * nb;
                auto fin = [&](int r, float t) {
                    float sr = 1.f / (1.f + __expf(-g_r2[c]));
                    g_x[c] = (g_x[c] + sr * t) * sc;
                };
                consume_body<1, HD>(w4, (const float4*)g_k2, 1, spart[i & 1], fin);
                consumed++;
            }
        }
        if (l < LNUM - 1) {
            kwl = kw + (size_t)(l + 1) * D * D;
            vwl = vw + (size_t)(l + 1) * D * D;
            rwl = rw + (size_t)(l + 1) * D * D;
            iA = 0; top_up(iA, nA, pbA);
        } else {
            iH = 0; top_up(iH, nH, pbH);
        }
        grid_barrier(nb);
    }

    // ---------- head ----------
    {
        float ss = 0.f;
        for (int j = tid; j < D; j += NT) { float t = g_x[j]; ss += t * t; }
        ss = block_sum(ss, sred);
        float inv = rsqrtf(ss * (1.f / D) + 1e-5f);
        for (int j = tid; j < D; j += NT) vecS[j] = g_x[j] * inv * lnout[j];
        __syncthreads();
        for (int i = 0; i < nH; i++) {
            top_up(iH, nH, pbH);
            const float4* w4 = ring_wait();
            int c = bid + i * nb;
            int re = VOCAB - c * 4; if (re > 4) re = 4;
            auto fin = [&](int r, float t) { out_logits[c * 4 + r] = t; };
            consume_body<4, D>(w4, vecS4, re, spart[i & 1], fin);
            consumed++;
        }
    }
}

extern "C" void kernel_launch(void* const* d_in, const int* in_sizes, int n_in,
                              void* d_out, int out_size) {
    (void)in_sizes; (void)n_in; (void)out_size;
    int nb = 0;
    cudaDeviceGetAttribute(&nb, cudaDevAttrMultiProcessorCount, 0);
    if (nb <= 0) nb = 148;
    if (nb > 512) nb = 512;   // keep every stage's chunk count >= nb

    const int smem_bytes = S_RING * SLOT_B;
    cudaFuncSetAttribute(rwkv_persistent,
                         cudaFuncAttributeMaxDynamicSharedMemorySize, smem_bytes);

    rwkv_persistent<<<nb, NT, smem_bytes>>>(
        (const int*)  d_in[0],   // ctx
        (const float*)d_in[1],   // state
        (const float*)d_in[2],   // emb
        (const float*)d_in[3],   // ln0_w
        (const float*)d_in[4],   // ln1_w
        (const float*)d_in[5],   // ln2_w
        (const float*)d_in[6],   // lnout_w
        (const float*)d_in[7],   // att_tmk
        (const float*)d_in[8],   // att_tmv
        (const float*)d_in[9],   // att_tmr
        (const float*)d_in[10],  // att_tfirst
        (const float*)d_in[11],  // att_tdecay
        (const float*)d_in[12],  // att_kw
        (const float*)d_in[13],  // att_vw
        (const float*)d_in[14],  // att_rw
        (const float*)d_in[15],  // att_ow
        (const float*)d_in[16],  // ffn_tmk
        (const float*)d_in[17],  // ffn_tmr
        (const float*)d_in[18],  // ffn_kw
        (const float*)d_in[19],  // ffn_vw
        (const float*)d_in[20],  // ffn_rw
        (const float*)d_in[21],  // head
        (float*)d_out, nb);
}

// round 7
// speedup vs baseline: 1.1943x; 1.1943x over previous
#include <cuda_runtime.h>

#define D      1024
#define HD     4096
#define LNUM   12
#define VOCAB  50257
#define NT     256
#define NW     8

// ---------------- global scratch ----------------
__device__ float g_xbuf[2][D];     // ping-pong pre-ow x per layer
__device__ float g_k[D], g_v[D], g_r[D];
__device__ float g_k2[HD];
__device__ float g_r2[D];
__device__ float g_accB[2][D];     // ow partial sums (ping-pong by layer parity)
__device__ float g_accD[2][D];     // fvw partial sums

// ---------------- 2-level software grid barrier ----------------
__device__ unsigned g_bar_gen = 0;
__device__ unsigned g_leaf[8 * 128];
__device__ unsigned g_root = 0;

__device__ __forceinline__ void grid_barrier(int nb) {
    __syncthreads();
    if (threadIdx.x == 0) {
        __threadfence();
        unsigned gen = *((volatile unsigned*)&g_bar_gen);
        int leaf = blockIdx.x & 7;
        unsigned target = (unsigned)((nb >> 3) + ((blockIdx.x & 7) < (nb & 7) ? 1 : 0));
        if (atomicAdd(&g_leaf[leaf * 128], 1u) == target - 1u) {
            g_leaf[leaf * 128] = 0;
            __threadfence();
            if (atomicAdd(&g_root, 1u) == 7u) {
                g_root = 0;
                __threadfence();
                atomicAdd(&g_bar_gen, 1u);
            }
        }
        while (*((volatile unsigned*)&g_bar_gen) == gen) { }
        __threadfence();
    }
    __syncthreads();
}

// ---------------- block-wide sum (8 warps) ----------------
__device__ __forceinline__ float block_sum(float v, float* sred) {
    int lane = threadIdx.x & 31, wid = threadIdx.x >> 5;
    #pragma unroll
    for (int o = 16; o; o >>= 1) v += __shfl_xor_sync(0xffffffffu, v, o);
    if (lane == 0) sred[wid] = v;
    __syncthreads();
    float t = 0.f;
    if (wid == 0) {
        t = (lane < NW) ? sred[lane] : 0.f;
        #pragma unroll
        for (int o = NW / 2; o; o >>= 1) t += __shfl_xor_sync(0xffffffffu, t, o);
        if (lane == 0) sred[0] = t;
    }
    __syncthreads();
    float r = sred[0];
    __syncthreads();
    return r;
}

// ---------------- warp dot: C batches of 512 floats, double-buffered 4x LDG.128 ----------------
template<int C>
__device__ __forceinline__ float dot512(const float* __restrict__ w,
                                        const float* __restrict__ vec) {
    const int lane = threadIdx.x & 31;
    const float4* __restrict__ w4 = reinterpret_cast<const float4*>(w);
    const float4* __restrict__ v4 = reinterpret_cast<const float4*>(vec);
    float4 A0 = __ldg(w4 + lane),      A1 = __ldg(w4 + 32 + lane);
    float4 A2 = __ldg(w4 + 64 + lane), A3 = __ldg(w4 + 96 + lane);
    float s0 = 0.f, s1 = 0.f, s2 = 0.f, s3 = 0.f;
    #pragma unroll
    for (int c = 0; c < C; c++) {
        float4 B0, B1, B2, B3;
        if (c + 1 < C) {
            const float4* wn = w4 + (c + 1) * 128;
            B0 = __ldg(wn + lane);      B1 = __ldg(wn + 32 + lane);
            B2 = __ldg(wn + 64 + lane); B3 = __ldg(wn + 96 + lane);
        }
        const float4* vc = v4 + c * 128;
        float4 b0 = vc[lane], b1 = vc[32 + lane], b2 = vc[64 + lane], b3 = vc[96 + lane];
        s0 = fmaf(A0.x, b0.x, s0); s1 = fmaf(A0.y, b0.y, s1);
        s2 = fmaf(A0.z, b0.z, s2); s3 = fmaf(A0.w, b0.w, s3);
        s0 = fmaf(A1.x, b1.x, s0); s1 = fmaf(A1.y, b1.y, s1);
        s2 = fmaf(A1.z, b1.z, s2); s3 = fmaf(A1.w, b1.w, s3);
        s0 = fmaf(A2.x, b2.x, s0); s1 = fmaf(A2.y, b2.y, s1);
        s2 = fmaf(A2.z, b2.z, s2); s3 = fmaf(A2.w, b2.w, s3);
        s0 = fmaf(A3.x, b3.x, s0); s1 = fmaf(A3.y, b3.y, s1);
        s2 = fmaf(A3.z, b3.z, s2); s3 = fmaf(A3.w, b3.w, s3);
        if (c + 1 < C) { A0 = B0; A1 = B1; A2 = B2; A3 = B3; }
    }
    float t = (s0 + s1) + (s2 + s3);
    #pragma unroll
    for (int o = 16; o; o >>= 1) t += __shfl_xor_sync(0xffffffffu, t, o);
    return t;
}

// 256-float quarter-row dot (stage B splits)
__device__ __forceinline__ float dot256(const float* __restrict__ w,
                                        const float* __restrict__ vec) {
    const int lane = threadIdx.x & 31;
    const float4* __restrict__ w4 = reinterpret_cast<const float4*>(w);
    const float4* __restrict__ v4 = reinterpret_cast<const float4*>(vec);
    float4 a0 = __ldg(w4 + lane), a1 = __ldg(w4 + 32 + lane);
    float4 b0 = v4[lane], b1 = v4[32 + lane];
    float s0 = fmaf(a0.x, b0.x, a0.y * b0.y);
    float s1 = fmaf(a0.z, b0.z, a0.w * b0.w);
    s0 = fmaf(a1.x, b1.x, s0); s1 = fmaf(a1.y, b1.y, s1);
    s0 = fmaf(a1.z, b1.z, s0); s1 = fmaf(a1.w, b1.w, s1);
    float t = s0 + s1;
    #pragma unroll
    for (int o = 16; o; o >>= 1) t += __shfl_xor_sync(0xffffffffu, t, o);
    return t;
}

__global__ __launch_bounds__(NT, 4) void rwkv_persistent(
    const int*   __restrict__ ctx,
    const float* __restrict__ st_in,
    const float* __restrict__ emb,
    const float* __restrict__ ln0,
    const float* __restrict__ ln1,
    const float* __restrict__ ln2,
    const float* __restrict__ lnout,
    const float* __restrict__ tmk,
    const float* __restrict__ tmv,
    const float* __restrict__ tmr,
    const float* __restrict__ tfirst,
    const float* __restrict__ tdecay,
    const float* __restrict__ kw,
    const float* __restrict__ vw,
    const float* __restrict__ rw,
    const float* __restrict__ ow,
    const float* __restrict__ ftmk,
    const float* __restrict__ ftmr,
    const float* __restrict__ fkw,
    const float* __restrict__ fvw,
    const float* __restrict__ frw,
    const float* __restrict__ head,
    float* __restrict__ out,
    int nb)
{
    __shared__ float vecS[HD];       // 16 KB
    __shared__ float sred[NW];

    const int tid  = threadIdx.x;
    const int lane = tid & 31;
    const int bid  = blockIdx.x;
    const int gw   = bid * NW + (tid >> 5);
    const int nwG  = nb * NW;

    float* out_logits = out;
    float* out_state  = out + VOCAB;

    // ---------- stage 0: embedding (block 0) ----------
    if (bid == 0) {
        const float* e = emb + (size_t)ctx[0] * D;
        float ss = 0.f;
        for (int j = tid; j < D; j += NT) { float t = e[j]; ss += t * t; }
        ss = block_sum(ss, sred);
        float inv = rsqrtf(ss * (1.f / D) + 1e-5f);
        for (int j = tid; j < D; j += NT) g_xbuf[0][j] = e[j] * inv * ln0[j];
    }
    grid_barrier(nb);

    for (int l = 0; l < LNUM; l++) {
        const int i0 = l & 1, i1 = i0 ^ 1;
        const int p  = l & 1;              // acc buffers this layer writes
        const int pr = p ^ 1;              // acc buffers from previous layer
        const float scp = (l > 0 && (l % 6 == 0)) ? 0.5f : 1.0f;  // prev layer's rescale
        const float* st_l  = st_in     + (size_t)l * 5 * D;
        float*       ost_l = out_state + (size_t)l * 5 * D;

        // ---------- stage A prep: fold prev-layer tail, rms, token-mix ----------
        {
            float ss = 0.f;
            for (int j = tid; j < D; j += NT) {
                float xv = g_xbuf[i0][j];
                if (l > 0) {
                    float sr = 1.f / (1.f + __expf(-g_r2[j]));
                    xv = (xv + g_accB[pr][j] + sr * g_accD[pr][j]) * scp;
                }
                vecS[3 * D + j] = xv;
                ss += xv * xv;
            }
            ss = block_sum(ss, sred);
            float inv = rsqrtf(ss * (1.f / D) + 1e-5f);
            const float* l1 = ln1 + l * D;
            const float* mk = tmk + l * D;
            const float* mv = tmv + l * D;
            const float* mr = tmr + l * D;
            for (int j = tid; j < D; j += NT) {
                float xv  = vecS[3 * D + j];
                float xxj = xv * inv * l1[j];
                float sa  = st_l[D + j];
                float a_ = mk[j]; vecS[j]         = xxj * a_ + sa * (1.f - a_);
                float b_ = mv[j]; vecS[D + j]     = xxj * b_ + sa * (1.f - b_);
                float c_ = mr[j]; vecS[2 * D + j] = xxj * c_ + sa * (1.f - c_);
                if (bid == 0) ost_l[D + j] = xxj;       // new sa_x
            }
            // materialize xn into the write buffer (blocks 0..3 cover all j once)
            if (bid < 4) g_xbuf[i1][bid * NT + tid] = vecS[3 * D + (bid * NT + tid)];
            // zero this layer's acc targets (blocks 4..7)
            if (bid >= 4 && bid < 8) {
                int j = (bid - 4) * NT + tid;
                g_accB[p][j] = 0.f;
                g_accD[p][j] = 0.f;
            }
            __syncthreads();
            // k/v/r matvecs: 3072 rows of 1024
            const float* kwl = kw + (size_t)l * D * D;
            const float* vwl = vw + (size_t)l * D * D;
            const float* rwl = rw + (size_t)l * D * D;
            for (int t = gw; t < 3 * D; t += nwG) {
                float r;
                if (t < D) {
                    r = dot512<2>(kwl + (size_t)t * D, vecS);
                    if (lane == 0) g_k[t] = r;
                } else if (t < 2 * D) {
                    r = dot512<2>(vwl + (size_t)(t - D) * D, vecS + D);
                    if (lane == 0) g_v[t - D] = r;
                } else {
                    r = dot512<2>(rwl + (size_t)(t - 2 * D) * D, vecS + 2 * D);
                    if (lane == 0) g_r[t - 2 * D] = r;
                }
            }
        }
        grid_barrier(nb);

        // ---------- stage B: WKV elementwise prep; ow quarter-row tasks ----------
        {
            const float* tfl = tfirst + l * D;
            const float* tdl = tdecay + l * D;
            for (int j = tid; j < D; j += NT) {
                float k  = g_k[j], v = g_v[j], rr = g_r[j];
                float aa = st_l[2 * D + j], bb = st_l[3 * D + j], pp = st_l[4 * D + j];
                float ww = tfl[j] + k;
                float pm = fmaxf(pp, ww);
                float e1 = __expf(pp - pm), e2 = __expf(ww - pm);
                float a  = e1 * aa + e2 * v;
                float b  = e1 * bb + e2;
                float sr = 1.f / (1.f + __expf(-rr));
                vecS[j] = sr * (a / b);
                if (bid == 0) {
                    float ww2 = pp + tdl[j];
                    float p2  = fmaxf(ww2, k);
                    float e1b = __expf(ww2 - p2), e2b = __expf(k - p2);
                    ost_l[2 * D + j] = e1b * aa + e2b * v;   // naa
                    ost_l[3 * D + j] = e1b * bb + e2b;       // nbb
                    ost_l[4 * D + j] = p2;                   // pp
                }
            }
            __syncthreads();
            const float* owl = ow + (size_t)l * D * D;
            for (int t = gw; t < 4 * D; t += nwG) {          // 4096 quarter-row tasks
                int row = t >> 2, q = t & 3;
                float pt = dot256(owl + (size_t)row * D + q * 256, vecS + q * 256);
                if (lane == 0) atomicAdd(&g_accB[p][row], pt);
            }
        }
        grid_barrier(nb);

        // ---------- stage C: fold accB, rms2, channel-mix prep; fkw/frw ----------
        {
            float ss = 0.f;
            for (int j = tid; j < D; j += NT) {
                float xv = g_xbuf[i1][j] + g_accB[p][j];
                vecS[3 * D + j] = xv;
                ss += xv * xv;
            }
            ss = block_sum(ss, sred);
            float inv = rsqrtf(ss * (1.f / D) + 1e-5f);
            const float* l2l = ln2  + l * D;
            const float* fmk = ftmk + l * D;
            const float* fmr = ftmr + l * D;
            for (int j = tid; j < D; j += NT) {
                float yyj = vecS[3 * D + j] * inv * l2l[j];
                float ff  = st_l[j];
                float a_ = fmk[j]; vecS[j]     = yyj * a_ + ff * (1.f - a_);
                float b_ = fmr[j]; vecS[D + j] = yyj * b_ + ff * (1.f - b_);
                if (bid == 0) ost_l[j] = yyj;                // new ff_x
            }
            __syncthreads();
            const float* fkwl = fkw + (size_t)l * HD * D;
            const float* frwl = frw + (size_t)l * D * D;
            for (int t = gw; t < HD + D; t += nwG) {
                if (t < HD) {
                    float r = dot512<2>(fkwl + (size_t)t * D, vecS);
                    if (lane == 0) { r = fmaxf(r, 0.f); g_k2[t] = r * r; }
                } else {
                    float r = dot512<2>(frwl + (size_t)(t - HD) * D, vecS + D);
                    if (lane == 0) g_r2[t - HD] = r;
                }
            }
        }
        grid_barrier(nb);

        // ---------- stage D: fvw quarter-row tasks into accD ----------
        {
            for (int j = tid; j < HD; j += NT) vecS[j] = g_k2[j];
            __syncthreads();
            const float* fvwl = fvw + (size_t)l * D * HD;
            for (int t = gw; t < 4 * D; t += nwG) {          // 4096 tasks of 1024 floats
                int row = t >> 2, c = t & 3;
                float pt = dot512<2>(fvwl + (size_t)row * HD + c * 1024, vecS + c * 1024);
                if (lane == 0) atomicAdd(&g_accD[p][row], pt);
            }
        }
        grid_barrier(nb);
    }

    // ---------- head: fold layer-11 tail, rms, logits ----------
    {
        const int i0 = LNUM & 1;           // = 0
        const int pr = (LNUM - 1) & 1;     // = 1
        const float scp = (LNUM % 6 == 0) ? 0.5f : 1.0f;
        float ss = 0.f;
        for (int j = tid; j < D; j += NT) {
            float sr = 1.f / (1.f + __expf(-g_r2[j]));
            float xv = (g_xbuf[i0][j] + g_accB[pr][j] + sr * g_accD[pr][j]) * scp;
            vecS[3 * D + j] = xv;
            ss += xv * xv;
        }
        ss = block_sum(ss, sred);
        float inv = rsqrtf(ss * (1.f / D) + 1e-5f);
        for (int j = tid; j < D; j += NT) vecS[j] = vecS[3 * D + j] * inv * lnout[j];
        __syncthreads();
        for (int t = gw; t < VOCAB; t += nwG) {
            float r = dot512<2>(head + (size_t)t * D, vecS);
            if (lane == 0) out_logits[t] = r;
        }
    }
}

extern "C" void kernel_launch(void* const* d_in, const int* in_sizes, int n_in,
                              void* d_out, int out_size) {
    (void)in_sizes; (void)n_in; (void)out_size;
    int nsm = 0;
    cudaDeviceGetAttribute(&nsm, cudaDevAttrMultiProcessorCount, 0);
    if (nsm <= 0) nsm = 148;

    int occ = 0;
    cudaOccupancyMaxActiveBlocksPerMultiprocessor(&occ, rwkv_persistent, NT, 0);
    if (occ <= 0) occ = 1;
    if (occ > 4) occ = 4;

    int nb = nsm * occ;
    if (nb > 1024) nb = 1024;

    rwkv_persistent<<<nb, NT>>>(
        (const int*)  d_in[0],   // ctx
        (const float*)d_in[1],   // state
        (const float*)d_in[2],   // emb
        (const float*)d_in[3],   // ln0_w
        (const float*)d_in[4],   // ln1_w
        (const float*)d_in[5],   // ln2_w
        (const float*)d_in[6],   // lnout_w
        (const float*)d_in[7],   // att_tmk
        (const float*)d_in[8],   // att_tmv
        (const float*)d_in[9],   // att_tmr
        (const float*)d_in[10],  // att_tfirst
        (const float*)d_in[11],  // att_tdecay
        (const float*)d_in[12],  // att_kw
        (const float*)d_in[13],  // att_vw
        (const float*)d_in[14],  // att_rw
        (const float*)d_in[15],  // att_ow
        (const float*)d_in[16],  // ffn_tmk
        (const float*)d_in[17],  // ffn_tmr
        (const float*)d_in[18],  // ffn_kw
        (const float*)d_in[19],  // ffn_vw
        (const float*)d_in[20],  // ffn_rw
        (const float*)d_in[21],  // head
        (float*)d_out, nb);
}

// round 8
// speedup vs baseline: 1.2211x; 1.0224x over previous
#include <cuda_runtime.h>

#define D      1024
#define HD     4096
#define LNUM   12
#define VOCAB  50257
#define NT     512
#define NW     16

// ---------------- global scratch ----------------
__device__ float g_xbuf[2][D];     // ping-pong pre-ow x per layer
__device__ float g_k[D], g_v[D], g_r[D];
__device__ float g_k2[HD];
__device__ float g_r2[D];
__device__ float g_accB[2][D];     // ow partial sums (ping-pong by layer parity)
__device__ float g_accD[2][D];     // fvw partial sums

// ---------------- 2-level software grid barrier ----------------
__device__ unsigned g_bar_gen = 0;
__device__ unsigned g_leaf[8 * 128];
__device__ unsigned g_root = 0;

__device__ __forceinline__ void grid_barrier(int nb) {
    __syncthreads();
    if (threadIdx.x == 0) {
        __threadfence();
        unsigned gen = *((volatile unsigned*)&g_bar_gen);
        int leaf = blockIdx.x & 7;
        unsigned target = (unsigned)((nb >> 3) + ((blockIdx.x & 7) < (nb & 7) ? 1 : 0));
        if (atomicAdd(&g_leaf[leaf * 128], 1u) == target - 1u) {
            g_leaf[leaf * 128] = 0;
            __threadfence();
            if (atomicAdd(&g_root, 1u) == 7u) {
                g_root = 0;
                __threadfence();
                atomicAdd(&g_bar_gen, 1u);
            }
        }
        while (*((volatile unsigned*)&g_bar_gen) == gen) { }
        __threadfence();
    }
    __syncthreads();
}

// ---------------- block-wide sum (16 warps) ----------------
__device__ __forceinline__ float block_sum(float v, float* sred) {
    int lane = threadIdx.x & 31, wid = threadIdx.x >> 5;
    #pragma unroll
    for (int o = 16; o; o >>= 1) v += __shfl_xor_sync(0xffffffffu, v, o);
    if (lane == 0) sred[wid] = v;
    __syncthreads();
    float t = 0.f;
    if (wid == 0) {
        t = (lane < NW) ? sred[lane] : 0.f;
        #pragma unroll
        for (int o = NW / 2; o; o >>= 1) t += __shfl_xor_sync(0xffffffffu, t, o);
        if (lane == 0) sred[0] = t;
    }
    __syncthreads();
    float r = sred[0];
    __syncthreads();
    return r;
}

// ---------------- pipelined item-stream dot ----------------
// Each item = NL*128 floats (NL LDG.128 per lane). While consuming item i,
// item i+1's loads are already in flight in the second register batch.
template<int NL, class GetPtr, class GetVec, class Fin>
__device__ __forceinline__ void pipe_dot(int n, int lane, GetPtr gp, GetVec gv, Fin fin) {
    if (n <= 0) return;
    float4 A[NL], Bq[NL];
    {
        const float4* p = gp(0);
        #pragma unroll
        for (int u = 0; u < NL; u++) A[u] = __ldg(p + u * 32 + lane);
    }
    for (int i = 0; i < n; i++) {
        if (i + 1 < n) {
            const float4* p = gp(i + 1);
            #pragma unroll
            for (int u = 0; u < NL; u++) Bq[u] = __ldg(p + u * 32 + lane);
        }
        const float4* v = gv(i);
        float s0 = 0.f, s1 = 0.f, s2 = 0.f, s3 = 0.f;
        #pragma unroll
        for (int u = 0; u < NL; u++) {
            float4 b = v[u * 32 + lane];
            s0 = fmaf(A[u].x, b.x, s0);
            s1 = fmaf(A[u].y, b.y, s1);
            s2 = fmaf(A[u].z, b.z, s2);
            s3 = fmaf(A[u].w, b.w, s3);
        }
        float t = (s0 + s1) + (s2 + s3);
        #pragma unroll
        for (int o = 16; o; o >>= 1) t += __shfl_xor_sync(0xffffffffu, t, o);
        fin(i, t);
        #pragma unroll
        for (int u = 0; u < NL; u++) A[u] = Bq[u];
    }
}

__global__ __launch_bounds__(NT, 1) void rwkv_persistent(
    const int*   __restrict__ ctx,
    const float* __restrict__ st_in,
    const float* __restrict__ emb,
    const float* __restrict__ ln0,
    const float* __restrict__ ln1,
    const float* __restrict__ ln2,
    const float* __restrict__ lnout,
    const float* __restrict__ tmk,
    const float* __restrict__ tmv,
    const float* __restrict__ tmr,
    const float* __restrict__ tfirst,
    const float* __restrict__ tdecay,
    const float* __restrict__ kw,
    const float* __restrict__ vw,
    const float* __restrict__ rw,
    const float* __restrict__ ow,
    const float* __restrict__ ftmk,
    const float* __restrict__ ftmr,
    const float* __restrict__ fkw,
    const float* __restrict__ fvw,
    const float* __restrict__ frw,
    const float* __restrict__ head,
    float* __restrict__ out,
    int nb)
{
    __shared__ float vecS[HD];       // 16 KB
    __shared__ float sred[NW];

    const int tid  = threadIdx.x;
    const int lane = tid & 31;
    const int bid  = blockIdx.x;
    const int gw   = bid * NW + (tid >> 5);
    const int nwG  = nb * NW;

    float* out_logits = out;
    float* out_state  = out + VOCAB;
    const float4* vecS4 = (const float4*)vecS;

    auto nmy = [&](int R) { return gw < R ? (R - 1 - gw) / nwG + 1 : 0; };

    // ---------- stage 0: embedding (block 0) ----------
    if (bid == 0) {
        const float* e = emb + (size_t)ctx[0] * D;
        float ss = 0.f;
        for (int j = tid; j < D; j += NT) { float t = e[j]; ss += t * t; }
        ss = block_sum(ss, sred);
        float inv = rsqrtf(ss * (1.f / D) + 1e-5f);
        for (int j = tid; j < D; j += NT) g_xbuf[0][j] = e[j] * inv * ln0[j];
    }
    grid_barrier(nb);

    for (int l = 0; l < LNUM; l++) {
        const int i0 = l & 1, i1 = i0 ^ 1;
        const int p  = l & 1;              // acc buffers this layer writes
        const int pr = p ^ 1;              // acc buffers from previous layer
        const float scp = (l > 0 && (l % 6 == 0)) ? 0.5f : 1.0f;  // prev layer's rescale
        const float* st_l  = st_in     + (size_t)l * 5 * D;
        float*       ost_l = out_state + (size_t)l * 5 * D;

        // ---------- stage A prep: fold prev-layer tail, rms, token-mix ----------
        {
            float ss = 0.f;
            for (int j = tid; j < D; j += NT) {
                float xv = g_xbuf[i0][j];
                if (l > 0) {
                    float sr = 1.f / (1.f + __expf(-g_r2[j]));
                    xv = (xv + g_accB[pr][j] + sr * g_accD[pr][j]) * scp;
                }
                vecS[3 * D + j] = xv;
                ss += xv * xv;
            }
            ss = block_sum(ss, sred);
            float inv = rsqrtf(ss * (1.f / D) + 1e-5f);
            const float* l1 = ln1 + l * D;
            const float* mk = tmk + l * D;
            const float* mv = tmv + l * D;
            const float* mr = tmr + l * D;
            for (int j = tid; j < D; j += NT) {
                float xv  = vecS[3 * D + j];
                float xxj = xv * inv * l1[j];
                float sa  = st_l[D + j];
                float a_ = mk[j]; vecS[j]         = xxj * a_ + sa * (1.f - a_);
                float b_ = mv[j]; vecS[D + j]     = xxj * b_ + sa * (1.f - b_);
                float c_ = mr[j]; vecS[2 * D + j] = xxj * c_ + sa * (1.f - c_);
                if (bid == 0) ost_l[D + j] = xxj;       // new sa_x
            }
            // materialize xn (blocks 0..1); zero acc targets (blocks 2..3)
            if (bid < 2) g_xbuf[i1][bid * NT + tid] = vecS[3 * D + (bid * NT + tid)];
            if (bid >= 2 && bid < 4) {
                int j = (bid - 2) * NT + tid;
                g_accB[p][j] = 0.f;
                g_accD[p][j] = 0.f;
            }
            __syncthreads();
            // k/v/r matvecs: 3072 rows of 1024
            const float* kwl = kw + (size_t)l * D * D;
            const float* vwl = vw + (size_t)l * D * D;
            const float* rwl = rw + (size_t)l * D * D;
            pipe_dot<8>(nmy(3 * D), lane,
                [&](int i) {
                    int t = gw + i * nwG;
                    int m = t >> 10, r = t & 1023;
                    const float* base = (m == 0) ? kwl : ((m == 1) ? vwl : rwl);
                    return (const float4*)(base + (size_t)r * D);
                },
                [&](int i) {
                    int t = gw + i * nwG;
                    return vecS4 + (t >> 10) * 256;
                },
                [&](int i, float t) {
                    if (lane == 0) {
                        int row = gw + i * nwG;
                        int m = row >> 10, r = row & 1023;
                        if (m == 0)      g_k[r] = t;
                        else if (m == 1) g_v[r] = t;
                        else             g_r[r] = t;
                    }
                });
        }
        grid_barrier(nb);

        // ---------- stage B: WKV elementwise prep; ow quarter-row tasks ----------
        {
            const float* tfl = tfirst + l * D;
            const float* tdl = tdecay + l * D;
            for (int j = tid; j < D; j += NT) {
                float k  = g_k[j], v = g_v[j], rr = g_r[j];
                float aa = st_l[2 * D + j], bb = st_l[3 * D + j], pp = st_l[4 * D + j];
                float ww = tfl[j] + k;
                float pm = fmaxf(pp, ww);
                float e1 = __expf(pp - pm), e2 = __expf(ww - pm);
                float a  = e1 * aa + e2 * v;
                float b  = e1 * bb + e2;
                float sr = 1.f / (1.f + __expf(-rr));
                vecS[j] = sr * (a / b);
                if (bid == 0) {
                    float ww2 = pp + tdl[j];
                    float p2  = fmaxf(ww2, k);
                    float e1b = __expf(ww2 - p2), e2b = __expf(k - p2);
                    ost_l[2 * D + j] = e1b * aa + e2b * v;   // naa
                    ost_l[3 * D + j] = e1b * bb + e2b;       // nbb
                    ost_l[4 * D + j] = p2;                   // pp
                }
            }
            __syncthreads();
            const float* owl = ow + (size_t)l * D * D;
            pipe_dot<2>(nmy(4 * D), lane,
                [&](int i) {
                    int t = gw + i * nwG;
                    return (const float4*)(owl + (size_t)(t >> 2) * D + (t & 3) * 256);
                },
                [&](int i) {
                    int t = gw + i * nwG;
                    return vecS4 + (t & 3) * 64;
                },
                [&](int i, float t) {
                    if (lane == 0) {
                        int task = gw + i * nwG;
                        atomicAdd(&g_accB[p][task >> 2], t);
                    }
                });
        }
        grid_barrier(nb);

        // ---------- stage C: fold accB, rms2, channel-mix prep; fkw/frw ----------
        {
            float ss = 0.f;
            for (int j = tid; j < D; j += NT) {
                float xv = g_xbuf[i1][j] + g_accB[p][j];
                vecS[3 * D + j] = xv;
                ss += xv * xv;
            }
            ss = block_sum(ss, sred);
            float inv = rsqrtf(ss * (1.f / D) + 1e-5f);
            const float* l2l = ln2  + l * D;
            const float* fmk = ftmk + l * D;
            const float* fmr = ftmr + l * D;
            for (int j = tid; j < D; j += NT) {
                float yyj = vecS[3 * D + j] * inv * l2l[j];
                float ff  = st_l[j];
                float a_ = fmk[j]; vecS[j]     = yyj * a_ + ff * (1.f - a_);
                float b_ = fmr[j]; vecS[D + j] = yyj * b_ + ff * (1.f - b_);
                if (bid == 0) ost_l[j] = yyj;                // new ff_x
            }
            __syncthreads();
            const float* fkwl = fkw + (size_t)l * HD * D;
            const float* frwl = frw + (size_t)l * D * D;
            pipe_dot<8>(nmy(HD + D), lane,
                [&](int i) {
                    int t = gw + i * nwG;
                    return (t < HD) ? (const float4*)(fkwl + (size_t)t * D)
                                    : (const float4*)(frwl + (size_t)(t - HD) * D);
                },
                [&](int i) {
                    int t = gw + i * nwG;
                    return (t < HD) ? vecS4 : (vecS4 + 256);
                },
                [&](int i, float t) {
                    if (lane == 0) {
                        int row = gw + i * nwG;
                        if (row < HD) { t = fmaxf(t, 0.f); g_k2[row] = t * t; }
                        else          g_r2[row - HD] = t;
                    }
                });
        }
        grid_barrier(nb);

        // ---------- stage D: fvw quarter-row tasks into accD ----------
        {
            for (int j = tid; j < HD; j += NT) vecS[j] = g_k2[j];
            __syncthreads();
            const float* fvwl = fvw + (size_t)l * D * HD;
            pipe_dot<8>(nmy(4 * D), lane,
                [&](int i) {
                    int t = gw + i * nwG;
                    return (const float4*)(fvwl + (size_t)(t >> 2) * HD + (t & 3) * 1024);
                },
                [&](int i) {
                    int t = gw + i * nwG;
                    return vecS4 + (t & 3) * 256;
                },
                [&](int i, float t) {
                    if (lane == 0) {
                        int task = gw + i * nwG;
                        atomicAdd(&g_accD[p][task >> 2], t);
                    }
                });
        }
        grid_barrier(nb);
    }

    // ---------- head: fold layer-11 tail, rms, logits ----------
    {
        const int i0 = LNUM & 1;           // = 0
        const int pr = (LNUM - 1) & 1;     // = 1
        const float scp = (LNUM % 6 == 0) ? 0.5f : 1.0f;
        float ss = 0.f;
        for (int j = tid; j < D; j += NT) {
            float sr = 1.f / (1.f + __expf(-g_r2[j]));
            float xv = (g_xbuf[i0][j] + g_accB[pr][j] + sr * g_accD[pr][j]) * scp;
            vecS[3 * D + j] = xv;
            ss += xv * xv;
        }
        ss = block_sum(ss, sred);
        float inv = rsqrtf(ss * (1.f / D) + 1e-5f);
        for (int j = tid; j < D; j += NT) vecS[j] = vecS[3 * D + j] * inv * lnout[j];
        __syncthreads();
        pipe_dot<8>(nmy(VOCAB), lane,
            [&](int i) {
                int t = gw + i * nwG;
                return (const float4*)(head + (size_t)t * D);
            },
            [&](int i) { (void)i; return vecS4; },
            [&](int i, float t) {
                if (lane == 0) out_logits[gw + i * nwG] = t;
            });
    }
}

extern "C" void kernel_launch(void* const* d_in, const int* in_sizes, int n_in,
                              void* d_out, int out_size) {
    (void)in_sizes; (void)n_in; (void)out_size;
    int nsm = 0;
    cudaDeviceGetAttribute(&nsm, cudaDevAttrMultiProcessorCount, 0);
    if (nsm <= 0) nsm = 148;
    int nb = nsm;
    if (nb > 1024) nb = 1024;

    rwkv_persistent<<<nb, NT>>>(
        (const int*)  d_in[0],   // ctx
        (const float*)d_in[1],   // state
        (const float*)d_in[2],   // emb
        (const float*)d_in[3],   // ln0_w
        (const float*)d_in[4],   // ln1_w
        (const float*)d_in[5],   // ln2_w
        (const float*)d_in[6],   // lnout_w
        (const float*)d_in[7],   // att_tmk
        (const float*)d_in[8],   // att_tmv
        (const float*)d_in[9],   // att_tmr
        (const float*)d_in[10],  // att_tfirst
        (const float*)d_in[11],  // att_tdecay
        (const float*)d_in[12],  // att_kw
        (const float*)d_in[13],  // att_vw
        (const float*)d_in[14],  // att_rw
        (const float*)d_in[15],  // att_ow
        (const float*)d_in[16],  // ffn_tmk
        (const float*)d_in[17],  // ffn_tmr
        (const float*)d_in[18],  // ffn_kw
        (const float*)d_in[19],  // ffn_vw
        (const float*)d_in[20],  // ffn_rw
        (const float*)d_in[21],  // head
        (float*)d_out, nb);
}

// round 9
// speedup vs baseline: 1.3661x; 1.1187x over previous
#include <cuda_runtime.h>

#define D     1024
#define HD    4096
#define LNUM  12
#define VOCAB 50257
#define NT    512
#define NW    16

// ---------------- global scratch ----------------
__device__ float g_x[D];
__device__ float g_k[D];
__device__ float g_v[D];
__device__ float g_r[D];
__device__ float g_k2[HD];
__device__ float g_r2[D];

// ---------------- barrier state ----------------
__device__ unsigned g_bar_gen = 0;
__device__ unsigned g_leaf[8 * 128];
__device__ unsigned g_root = 0;

// ---------------- cp.async / prefetch helpers ----------------
__device__ __forceinline__ void cp16s(float* s, const float4* g) {
    unsigned sa = (unsigned)__cvta_generic_to_shared(s);
    asm volatile("cp.async.ca.shared.global [%0], [%1], 16;" :: "r"(sa), "l"(g));
}
__device__ __forceinline__ void cp_commit_g() {
    asm volatile("cp.async.commit_group;" ::: "memory");
}
__device__ __forceinline__ void cp_wait_all_g() {
    asm volatile("cp.async.wait_all;" ::: "memory");
}
__device__ __forceinline__ void l2pf(const float* p) {
    asm volatile("prefetch.global.L2 [%0];" :: "l"(p));
}

// stage up to 5 rows of 1024 floats into stg (cp.async, threads 0..255)
__device__ __forceinline__ void stage5(float* stg, int tid,
        const float* p0, const float* p1, const float* p2,
        const float* p3, const float* p4) {
    if (tid < 256) {
        if (p0) cp16s(stg +        tid * 4, (const float4*)p0 + tid);
        if (p1) cp16s(stg + 1024 + tid * 4, (const float4*)p1 + tid);
        if (p2) cp16s(stg + 2048 + tid * 4, (const float4*)p2 + tid);
        if (p3) cp16s(stg + 3072 + tid * 4, (const float4*)p3 + tid);
        if (p4) cp16s(stg + 4096 + tid * 4, (const float4*)p4 + tid);
        cp_commit_g();
    }
}

// ---------------- split grid barrier ----------------
__device__ __forceinline__ void gb_arrive(int nb, volatile unsigned* s_gen) {
    __threadfence();
    __syncthreads();
    if (threadIdx.x == 0) {
        *s_gen = *((volatile unsigned*)&g_bar_gen);
        int leaf = blockIdx.x & 7;
        unsigned target = (unsigned)((nb >> 3) + ((blockIdx.x & 7) < (nb & 7) ? 1 : 0));
        if (atomicAdd(&g_leaf[leaf * 128], 1u) == target - 1u) {
            g_leaf[leaf * 128] = 0;
            __threadfence();
            if (atomicAdd(&g_root, 1u) == 7u) {
                g_root = 0;
                __threadfence();
                atomicAdd(&g_bar_gen, 1u);
            }
        }
    }
}
__device__ __forceinline__ void gb_wait(volatile unsigned* s_gen) {
    if (threadIdx.x == 0) {
        unsigned gen = *s_gen;
        while (*((volatile unsigned*)&g_bar_gen) == gen) { }
        __threadfence();   // gpu-scope fence: invalidates L1 (coherence w/ other SMs)
    }
    __syncthreads();
}

// ---------------- block-wide sum ----------------
__device__ __forceinline__ float block_sum(float v, float* sred) {
    int lane = threadIdx.x & 31, wid = threadIdx.x >> 5;
    #pragma unroll
    for (int o = 16; o; o >>= 1) v += __shfl_xor_sync(0xffffffffu, v, o);
    if (lane == 0) sred[wid] = v;
    __syncthreads();
    float t = 0.f;
    if (wid == 0) {
        t = (lane < NW) ? sred[lane] : 0.f;
        #pragma unroll
        for (int o = 8; o; o >>= 1) t += __shfl_xor_sync(0xffffffffu, t, o);
        if (lane == 0) sred[0] = t;
    }
    __syncthreads();
    float r = sred[0];
    __syncthreads();
    return r;
}

// ---------------- warp dot: NB8 batches of 1024 floats, 8 batched LDG.128 ----------------
template<int NB8>
__device__ __forceinline__ float warp_dotN(const float* __restrict__ w,
                                           const float* __restrict__ vec) {
    const int lane = threadIdx.x & 31;
    const float4* __restrict__ w4 = reinterpret_cast<const float4*>(w);
    const float4* __restrict__ v4 = reinterpret_cast<const float4*>(vec);
    float ax = 0.f, ay = 0.f, az = 0.f, aw = 0.f;
    #pragma unroll
    for (int b = 0; b < NB8; b++) {
        float4 a[8];
        #pragma unroll
        for (int i = 0; i < 8; i++)
            a[i] = __ldg(w4 + b * 256 + i * 32 + lane);
        #pragma unroll
        for (int i = 0; i < 8; i++) {
            float4 bv = v4[b * 256 + i * 32 + lane];
            ax = fmaf(a[i].x, bv.x, ax);
            ay = fmaf(a[i].y, bv.y, ay);
            az = fmaf(a[i].z, bv.z, az);
            aw = fmaf(a[i].w, bv.w, aw);
        }
    }
    float acc = (ax + ay) + (az + aw);
    #pragma unroll
    for (int o = 16; o; o >>= 1) acc += __shfl_xor_sync(0xffffffffu, acc, o);
    return acc;
}

__global__ __launch_bounds__(NT, 1) void rwkv_persistent(
    const int*   __restrict__ ctx,
    const float* __restrict__ st_in,
    const float* __restrict__ emb,
    const float* __restrict__ ln0,
    const float* __restrict__ ln1,
    const float* __restrict__ ln2,
    const float* __restrict__ lnout,
    const float* __restrict__ tmk,
    const float* __restrict__ tmv,
    const float* __restrict__ tmr,
    const float* __restrict__ tfirst,
    const float* __restrict__ tdecay,
    const float* __restrict__ kw,
    const float* __restrict__ vw,
    const float* __restrict__ rw,
    const float* __restrict__ ow,
    const float* __restrict__ ftmk,
    const float* __restrict__ ftmr,
    const float* __restrict__ fkw,
    const float* __restrict__ fvw,
    const float* __restrict__ frw,
    const float* __restrict__ head,
    float* __restrict__ out,
    int nb)
{
    __shared__ float vecS[3 * D];     // 12 KB
    __shared__ float stg[5 * 1024];   // 20 KB param/state staging
    __shared__ float sred[NW];
    __shared__ unsigned s_gen;

    const int tid  = threadIdx.x;
    const int lane = tid & 31;
    const int bid  = blockIdx.x;
    const int gw   = bid * NW + (tid >> 5);
    const int nwG  = nb * NW;

    float* out_logits = out;
    float* out_state  = out + VOCAB;
    const float* vS = vecS;

    // ---------- prologue: stage layer-0 A params; embedding (block 0) ----------
    stage5(stg, tid, ln1, tmk, tmv, tmr, st_in + D);
    {
        int t = gw;
        if (t < 3 * D) {
            int m = t >> 10, r = t & 1023;
            const float* base = (m == 0) ? kw : ((m == 1) ? vw : rw);
            l2pf(base + (size_t)r * D + lane * 32);
        }
    }
    if (bid == 0) {
        const float* e = emb + (size_t)ctx[0] * D;
        float ss = 0.f;
        for (int j = tid; j < D; j += NT) { float t = e[j]; ss += t * t; }
        ss = block_sum(ss, sred);
        float inv = rsqrtf(ss * (1.f / D) + 1e-5f);
        for (int j = tid; j < D; j += NT) g_x[j] = e[j] * inv * ln0[j];
    }
    gb_arrive(nb, &s_gen);
    cp_wait_all_g();
    gb_wait(&s_gen);

    for (int l = 0; l < LNUM; l++) {
        const float* st_l  = st_in     + (size_t)l * 5 * D;
        float*       ost_l = out_state + (size_t)l * 5 * D;

        // ================= stage A: rms + token-mix prep; k/v/r matvecs =================
        {
            float ss = 0.f;
            for (int j = tid; j < D; j += NT) { float t = g_x[j]; ss += t * t; }
            ss = block_sum(ss, sred);
            float inv = rsqrtf(ss * (1.f / D) + 1e-5f);
            // staged: stg0=ln1, stg1=tmk, stg2=tmv, stg3=tmr, stg4=sa_x
            for (int j = tid; j < D; j += NT) {
                float xxj = g_x[j] * inv * stg[j];
                float sa  = stg[4096 + j];
                float a_ = stg[1024 + j]; vecS[j]         = xxj * a_ + sa * (1.f - a_);
                float b_ = stg[2048 + j]; vecS[D + j]     = xxj * b_ + sa * (1.f - b_);
                float c_ = stg[3072 + j]; vecS[2 * D + j] = xxj * c_ + sa * (1.f - c_);
                if (bid == 0) ost_l[D + j] = xxj;   // new sa_x
            }
            __syncthreads();
            const float* kwl = kw + (size_t)l * D * D;
            const float* vwl = vw + (size_t)l * D * D;
            const float* rwl = rw + (size_t)l * D * D;
            for (int t = gw; t < 3 * D; t += nwG) {
                int m = t >> 10, r = t & 1023;
                const float* base = (m == 0) ? kwl : ((m == 1) ? vwl : rwl);
                float acc = warp_dotN<1>(base + (size_t)r * D, vS + m * 1024);
                if (lane == 0) {
                    if (m == 0)      g_k[r] = acc;
                    else if (m == 1) g_v[r] = acc;
                    else             g_r[r] = acc;
                }
            }
        }
        gb_arrive(nb, &s_gen);
        stage5(stg, tid, tfirst + l * D, tdecay + l * D,
               st_l + 2 * D, st_l + 3 * D, st_l + 4 * D);
        if (gw < D) l2pf(ow + (size_t)l * D * D + (size_t)gw * D + lane * 32);
        cp_wait_all_g();
        gb_wait(&s_gen);

        // ================= stage B: WKV prep; ow matvec =================
        {
            // staged: stg0=tfirst, stg1=tdecay, stg2=aa, stg3=bb, stg4=pp
            for (int j = tid; j < D; j += NT) {
                float k  = g_k[j], v = g_v[j], rr = g_r[j];
                float aa = stg[2048 + j], bb = stg[3072 + j], pp = stg[4096 + j];
                float ww = stg[j] + k;
                float p  = fmaxf(pp, ww);
                float e1 = __expf(pp - p), e2 = __expf(ww - p);
                float a  = e1 * aa + e2 * v;
                float b  = e1 * bb + e2;
                float sr = 1.f / (1.f + __expf(-rr));
                vecS[j] = sr * (a / b);
                if (bid == 0) {
                    float ww2 = pp + stg[1024 + j];
                    float p2  = fmaxf(ww2, k);
                    float e1b = __expf(ww2 - p2), e2b = __expf(k - p2);
                    ost_l[2 * D + j] = e1b * aa + e2b * v;   // naa
                    ost_l[3 * D + j] = e1b * bb + e2b;       // nbb
                    ost_l[4 * D + j] = p2;                   // pp
                }
            }
            __syncthreads();
            const float* owl = ow + (size_t)l * D * D;
            for (int t = gw; t < D; t += nwG) {
                float dv = warp_dotN<1>(owl + (size_t)t * D, vS);
                if (lane == 0) g_x[t] += dv;
            }
        }
        gb_arrive(nb, &s_gen);
        stage5(stg, tid, ln2 + l * D, ftmk + l * D, ftmr + l * D, st_l, 0);
        {
            int t = gw;
            if (t < HD) l2pf(fkw + (size_t)l * HD * D + (size_t)t * D + lane * 32);
            else if (t < HD + D) l2pf(frw + (size_t)l * D * D + (size_t)(t - HD) * D + lane * 32);
        }
        cp_wait_all_g();
        gb_wait(&s_gen);

        // ================= stage C: rms2 + channel-mix prep; fkw/frw =================
        {
            float ss = 0.f;
            for (int j = tid; j < D; j += NT) { float t = g_x[j]; ss += t * t; }
            ss = block_sum(ss, sred);
            float inv = rsqrtf(ss * (1.f / D) + 1e-5f);
            // staged: stg0=ln2, stg1=ftmk, stg2=ftmr, stg3=ff_x
            for (int j = tid; j < D; j += NT) {
                float yyj = g_x[j] * inv * stg[j];
                float ff  = stg[3072 + j];
                float a_ = stg[1024 + j]; vecS[j]     = yyj * a_ + ff * (1.f - a_);
                float b_ = stg[2048 + j]; vecS[D + j] = yyj * b_ + ff * (1.f - b_);
                if (bid == 0) ost_l[j] = yyj;   // new ff_x
            }
            __syncthreads();
            const float* fkwl = fkw + (size_t)l * HD * D;
            const float* frwl = frw + (size_t)l * D * D;
            for (int t = gw; t < HD + D; t += nwG) {
                if (t < HD) {
                    float r = warp_dotN<1>(fkwl + (size_t)t * D, vS);
                    if (lane == 0) { r = fmaxf(r, 0.f); g_k2[t] = r * r; }
                } else {
                    float r = warp_dotN<1>(frwl + (size_t)(t - HD) * D, vS + D);
                    if (lane == 0) g_r2[t - HD] = r;
                }
            }
        }
        gb_arrive(nb, &s_gen);
        if (gw < D) l2pf(fvw + (size_t)l * D * HD + (size_t)gw * HD + lane * 32);
        gb_wait(&s_gen);

        // ================= stage D: fvw matvec (vec = g_k2 direct from L2/L1) =================
        {
            const float sc = ((l + 1) % 6 == 0) ? 0.5f : 1.0f;
            const float* fvwl = fvw + (size_t)l * D * HD;
            for (int t = gw; t < D; t += nwG) {
                float acc = warp_dotN<4>(fvwl + (size_t)t * HD, (const float*)g_k2);
                if (lane == 0) {
                    float sr = 1.f / (1.f + __expf(-g_r2[t]));
                    g_x[t] = (g_x[t] + sr * acc) * sc;
                }
            }
        }
        gb_arrive(nb, &s_gen);
        if (l < LNUM - 1) {
            stage5(stg, tid, ln1 + (l + 1) * D, tmk + (l + 1) * D,
                   tmv + (l + 1) * D, tmr + (l + 1) * D,
                   st_in + (size_t)(l + 1) * 5 * D + D);
            int t = gw;
            if (t < 3 * D) {
                int m = t >> 10, r = t & 1023;
                const float* base = (m == 0) ? kw : ((m == 1) ? vw : rw);
                l2pf(base + (size_t)(l + 1) * D * D + (size_t)r * D + lane * 32);
            }
        } else {
            stage5(stg, tid, lnout, 0, 0, 0, 0);
            l2pf(head + (size_t)gw * D + lane * 32);
            if (gw + nwG < VOCAB) l2pf(head + (size_t)(gw + nwG) * D + lane * 32);
        }
        cp_wait_all_g();
        gb_wait(&s_gen);
    }

    // ================= head: rms + logits (dual-row interleaved) =================
    {
        float ss = 0.f;
        for (int j = tid; j < D; j += NT) { float t = g_x[j]; ss += t * t; }
        ss = block_sum(ss, sred);
        float inv = rsqrtf(ss * (1.f / D) + 1e-5f);
        for (int j = tid; j < D; j += NT) vecS[j] = g_x[j] * inv * stg[j];
        __syncthreads();

        const float4* v4 = (const float4*)vecS;
        int nH = (gw < VOCAB) ? (VOCAB - 1 - gw) / nwG + 1 : 0;
        int i = 0;
        for (; i + 1 < nH; i += 2) {
            int t0 = gw + i * nwG, t1 = t0 + nwG;
            const float4* w0 = (const float4*)(head + (size_t)t0 * D);
            const float4* w1 = (const float4*)(head + (size_t)t1 * D);
            float4 a0[8], a1[8];
            #pragma unroll
            for (int u = 0; u < 8; u++) a0[u] = __ldg(w0 + u * 32 + lane);
            #pragma unroll
            for (int u = 0; u < 8; u++) a1[u] = __ldg(w1 + u * 32 + lane);
            float x0 = 0.f, y0 = 0.f, z0 = 0.f, q0 = 0.f;
            #pragma unroll
            for (int u = 0; u < 8; u++) {
                float4 b = v4[u * 32 + lane];
                x0 = fmaf(a0[u].x, b.x, x0); y0 = fmaf(a0[u].y, b.y, y0);
                z0 = fmaf(a0[u].z, b.z, z0); q0 = fmaf(a0[u].w, b.w, q0);
            }
            float r0 = (x0 + y0) + (z0 + q0);
            #pragma unroll
            for (int o = 16; o; o >>= 1) r0 += __shfl_xor_sync(0xffffffffu, r0, o);
            if (lane == 0) out_logits[t0] = r0;
            float x1 = 0.f, y1 = 0.f, z1 = 0.f, q1 = 0.f;
            #pragma unroll
            for (int u = 0; u < 8; u++) {
                float4 b = v4[u * 32 + lane];
                x1 = fmaf(a1[u].x, b.x, x1); y1 = fmaf(a1[u].y, b.y, y1);
                z1 = fmaf(a1[u].z, b.z, z1); q1 = fmaf(a1[u].w, b.w, q1);
            }
            float r1 = (x1 + y1) + (z1 + q1);
            #pragma unroll
            for (int o = 16; o; o >>= 1) r1 += __shfl_xor_sync(0xffffffffu, r1, o);
            if (lane == 0) out_logits[t1] = r1;
        }
        if (i < nH) {
            int t0 = gw + i * nwG;
            float r = warp_dotN<1>(head + (size_t)t0 * D, vS);
            if (lane == 0) out_logits[t0] = r;
        }
    }
}

extern "C" void kernel_launch(void* const* d_in, const int* in_sizes, int n_in,
                              void* d_out, int out_size) {
    (void)in_sizes; (void)n_in; (void)out_size;
    int nb = 0;
    cudaDeviceGetAttribute(&nb, cudaDevAttrMultiProcessorCount, 0);
    if (nb <= 0) nb = 148;
    if (nb > 1024) nb = 1024;

    rwkv_persistent<<<nb, NT>>>(
        (const int*)  d_in[0],   // ctx
        (const float*)d_in[1],   // state
        (const float*)d_in[2],   // emb
        (const float*)d_in[3],   // ln0_w
        (const float*)d_in[4],   // ln1_w
        (const float*)d_in[5],   // ln2_w
        (const float*)d_in[6],   // lnout_w
        (const float*)d_in[7],   // att_tmk
        (const float*)d_in[8],   // att_tmv
        (const float*)d_in[9],   // att_tmr
        (const float*)d_in[10],  // att_tfirst
        (const float*)d_in[11],  // att_tdecay
        (const float*)d_in[12],  // att_kw
        (const float*)d_in[13],  // att_vw
        (const float*)d_in[14],  // att_rw
        (const float*)d_in[15],  // att_ow
        (const float*)d_in[16],  // ffn_tmk
        (const float*)d_in[17],  // ffn_tmr
        (const float*)d_in[18],  // ffn_kw
        (const float*)d_in[19],  // ffn_vw
        (const float*)d_in[20],  // ffn_rw
        (const float*)d_in[21],  // head
        (float*)d_out, nb);
}